// round 5
// baseline (speedup 1.0000x reference)
#include <cuda_runtime.h>
#include <cuda_bf16.h>

// Problem constants
#define BATCH 16
#define CH    512
#define HW    48
#define NPIX  2304          // 48*48
#define IDIM  64            // inter channels

// ---------------------------------------------------------------------------
// Device scratch (allocation-free rule: __device__ globals)
// ---------------------------------------------------------------------------
__device__ float g_q[(size_t)BATCH * IDIM * NPIX];   //  9.4 MB
__device__ float g_k[(size_t)BATCH * IDIM * NPIX];   //  9.4 MB
__device__ float g_v[(size_t)BATCH * CH   * NPIX];   // 75.5 MB
__device__ float g_s[(size_t)BATCH * NPIX * NPIX];   // 339.7 MB

// ---------------------------------------------------------------------------
// Generic batched tiled SGEMM:  C[m,n] = sum_k A(m,k) * B(k,n)
//   A_KM: A element (m,k) = A[m*lda + k]   else A[k*lda + m]
//   B_KM: B element (k,n) = B[n*ldb + k]   else B[k*ldb + n]
//   EPI : C = gamma[0]*acc + X (X has same layout/stride as C)
// Requirements: N % 128 == 0, K % 16 == 0 (true for all call sites);
//               M handled with bounds guards.
// ---------------------------------------------------------------------------
template <bool A_KM, bool B_KM, bool EPI>
__global__ void __launch_bounds__(256)
gemm_kernel(const float* __restrict__ A, int lda, long long strideA,
            const float* __restrict__ B, int ldb, long long strideB,
            float* __restrict__ C, int ldc, long long strideC,
            int M, int N, int K,
            const float* __restrict__ gamma,
            const float* __restrict__ X, long long strideX)
{
    constexpr int BM = 128, BN = 128, BK = 16, TM = 8, TN = 8;
    __shared__ float As[BK][BM + 4];
    __shared__ float Bs[BK][BN + 4];

    const int b = blockIdx.z;
    A += (size_t)b * strideA;
    B += (size_t)b * strideB;
    C += (size_t)b * strideC;

    const int tid  = threadIdx.x;
    const int tx   = tid & 15;        // 0..15 -> column group
    const int ty   = tid >> 4;        // 0..15 -> row group
    const int row0 = blockIdx.y * BM;
    const int col0 = blockIdx.x * BN;

    float acc[TM][TN] = {};

    for (int kt = 0; kt < K; kt += BK) {
        // ---- load A tile into As[k][m] ----
        if (A_KM) {
            #pragma unroll
            for (int i = tid; i < BM * BK; i += 256) {
                int m  = i / BK;
                int kk = i % BK;
                int gm = row0 + m;
                float v = (gm < M) ? A[(size_t)gm * lda + (kt + kk)] : 0.0f;
                As[kk][m] = v;
            }
        } else {
            #pragma unroll
            for (int i = tid; i < BK * BM; i += 256) {
                int kk = i / BM;
                int m  = i % BM;
                int gm = row0 + m;
                float v = (gm < M) ? A[(size_t)(kt + kk) * lda + gm] : 0.0f;
                As[kk][m] = v;
            }
        }
        // ---- load B tile into Bs[k][n] ----
        if (B_KM) {
            #pragma unroll
            for (int i = tid; i < BN * BK; i += 256) {
                int n  = i / BK;
                int kk = i % BK;
                Bs[kk][n] = B[(size_t)(col0 + n) * ldb + (kt + kk)];
            }
        } else {
            #pragma unroll
            for (int i = tid; i < BK * BN; i += 256) {
                int kk = i / BN;
                int n  = i % BN;
                Bs[kk][n] = B[(size_t)(kt + kk) * ldb + (col0 + n)];
            }
        }
        __syncthreads();

        // ---- FMA microkernel: 8x8 per thread ----
        #pragma unroll
        for (int kk = 0; kk < BK; kk++) {
            float af[TM], bf[TN];
            #pragma unroll
            for (int i = 0; i < TM; i++) af[i] = As[kk][ty * TM + i];
            #pragma unroll
            for (int j = 0; j < TN; j++) bf[j] = Bs[kk][tx * TN + j];
            #pragma unroll
            for (int i = 0; i < TM; i++)
                #pragma unroll
                for (int j = 0; j < TN; j++)
                    acc[i][j] += af[i] * bf[j];
        }
        __syncthreads();
    }

    // ---- epilogue ----
    const float g = EPI ? gamma[0] : 0.0f;
    const float* Xb = EPI ? (X + (size_t)b * strideX) : nullptr;
    #pragma unroll
    for (int i = 0; i < TM; i++) {
        int gm = row0 + ty * TM + i;
        if (gm >= M) continue;
        #pragma unroll
        for (int j = 0; j < TN; j++) {
            int gn = col0 + tx * TN + j;
            float r = acc[i][j];
            if (EPI) r = g * r + Xb[(size_t)gm * ldc + gn];
            C[(size_t)gm * ldc + gn] = r;
        }
    }
}

// ---------------------------------------------------------------------------
// Row softmax over last dim of S[b][n][m], m = 0..NPIX-1.
// 2304 = 9 * 256 -> the whole row lives in registers: one read + one write.
// ---------------------------------------------------------------------------
__global__ void __launch_bounds__(256)
softmax_kernel(float* __restrict__ S)
{
    const int n = blockIdx.x;
    const int b = blockIdx.y;
    float* row = S + ((size_t)b * NPIX + n) * NPIX;

    const int tid  = threadIdx.x;
    const int lane = tid & 31;
    const int warp = tid >> 5;

    float vals[9];
    float mx = -1e30f;
    #pragma unroll
    for (int j = 0; j < 9; j++) {
        vals[j] = row[tid + j * 256];
        mx = fmaxf(mx, vals[j]);
    }

    __shared__ float smax[8];
    __shared__ float ssum[8];
    __shared__ float sbc[2];

    // block max
    #pragma unroll
    for (int o = 16; o > 0; o >>= 1)
        mx = fmaxf(mx, __shfl_xor_sync(0xffffffffu, mx, o));
    if (lane == 0) smax[warp] = mx;
    __syncthreads();
    if (tid == 0) {
        float m = smax[0];
        #pragma unroll
        for (int i = 1; i < 8; i++) m = fmaxf(m, smax[i]);
        sbc[0] = m;
    }
    __syncthreads();
    mx = sbc[0];

    // exp + block sum
    float s = 0.0f;
    #pragma unroll
    for (int j = 0; j < 9; j++) {
        vals[j] = __expf(vals[j] - mx);
        s += vals[j];
    }
    #pragma unroll
    for (int o = 16; o > 0; o >>= 1)
        s += __shfl_xor_sync(0xffffffffu, s, o);
    if (lane == 0) ssum[warp] = s;
    __syncthreads();
    if (tid == 0) {
        float t = ssum[0];
        #pragma unroll
        for (int i = 1; i < 8; i++) t += ssum[i];
        sbc[1] = 1.0f / t;
    }
    __syncthreads();
    const float inv = sbc[1];

    #pragma unroll
    for (int j = 0; j < 9; j++)
        row[tid + j * 256] = vals[j] * inv;
}

// ---------------------------------------------------------------------------
// kernel_launch: x, Wq, Wk, Wv, gamma  ->  out (fp32, B*C*H*W)
// ---------------------------------------------------------------------------
extern "C" void kernel_launch(void* const* d_in, const int* in_sizes, int n_in,
                              void* d_out, int out_size)
{
    const float* x     = (const float*)d_in[0];
    const float* Wq    = (const float*)d_in[1];
    const float* Wk    = (const float*)d_in[2];
    const float* Wv    = (const float*)d_in[3];
    const float* gamma = (const float*)d_in[4];
    float* out = (float*)d_out;

    float *qp, *kp, *vp, *sp;
    cudaGetSymbolAddress((void**)&qp, g_q);
    cudaGetSymbolAddress((void**)&kp, g_k);
    cudaGetSymbolAddress((void**)&vp, g_v);
    cudaGetSymbolAddress((void**)&sp, g_s);

    const long long sx = (long long)CH * NPIX;    // x / v / out per-batch stride
    const long long sq = (long long)IDIM * NPIX;  // q / k per-batch stride
    const long long ss = (long long)NPIX * NPIX;  // scores per-batch stride
    const int NB = NPIX / 128;                    // 18

    // q = Wq @ x : (64 x 512) * (512 x 2304)
    gemm_kernel<true, false, false><<<dim3(NB, 1, BATCH), 256>>>(
        Wq, CH, 0, x, NPIX, sx, qp, NPIX, sq,
        IDIM, NPIX, CH, nullptr, nullptr, 0);

    // k = Wk @ x
    gemm_kernel<true, false, false><<<dim3(NB, 1, BATCH), 256>>>(
        Wk, CH, 0, x, NPIX, sx, kp, NPIX, sq,
        IDIM, NPIX, CH, nullptr, nullptr, 0);

    // v = Wv @ x : (512 x 512) * (512 x 2304)
    gemm_kernel<true, false, false><<<dim3(NB, CH / 128, BATCH), 256>>>(
        Wv, CH, 0, x, NPIX, sx, vp, NPIX, sx,
        CH, NPIX, CH, nullptr, nullptr, 0);

    // S[n,m] = sum_i q[i,n] * k[i,m] : (2304 x 64) * (64 x 2304)
    gemm_kernel<false, false, false><<<dim3(NB, NB, BATCH), 256>>>(
        qp, NPIX, sq, kp, NPIX, sq, sp, NPIX, ss,
        NPIX, NPIX, IDIM, nullptr, nullptr, 0);

    // softmax over m (row-wise)
    softmax_kernel<<<dim3(NPIX, BATCH), 256>>>(sp);

    // out[c,n] = gamma * sum_m v[c,m] * P[n,m] + x[c,n]
    gemm_kernel<true, true, true><<<dim3(NB, CH / 128, BATCH), 256>>>(
        vp, NPIX, sx, sp, NPIX, ss, out, NPIX, sx,
        CH, NPIX, NPIX, gamma, x, sx);
}

// round 6
// speedup vs baseline: 1.6605x; 1.6605x over previous
#include <cuda_runtime.h>
#include <cuda_bf16.h>

// Problem constants
#define BATCH 16
#define CH    512
#define HW    48
#define NPIX  2304          // 48*48
#define IDIM  64            // inter channels

// ---------------------------------------------------------------------------
// Device scratch (allocation-free rule: __device__ globals)
// ---------------------------------------------------------------------------
__device__ float g_q[(size_t)BATCH * IDIM * NPIX];   //  9.4 MB
__device__ float g_k[(size_t)BATCH * IDIM * NPIX];   //  9.4 MB
__device__ float g_v[(size_t)BATCH * CH   * NPIX];   // 75.5 MB
__device__ float g_s[(size_t)BATCH * NPIX * NPIX];   // 339.7 MB

// ===========================================================================
// fp32 SIMT GEMM (kept for q, k, scores — softmax logits must stay exact).
//   C[m,n] = sum_k A(m,k) * B(k,n)
//   A_KM: A element (m,k) = A[m*lda + k]   else A[k*lda + m]
//   B_KM: B element (k,n) = B[n*ldb + k]   else B[k*ldb + n]
// ===========================================================================
template <bool A_KM, bool B_KM, bool EPI>
__global__ void __launch_bounds__(256)
gemm_kernel(const float* __restrict__ A, int lda, long long strideA,
            const float* __restrict__ B, int ldb, long long strideB,
            float* __restrict__ C, int ldc, long long strideC,
            int M, int N, int K,
            const float* __restrict__ gamma,
            const float* __restrict__ X, long long strideX)
{
    constexpr int BM = 128, BN = 128, BK = 16, TM = 8, TN = 8;
    __shared__ float As[BK][BM + 4];
    __shared__ float Bs[BK][BN + 4];

    const int b = blockIdx.z;
    A += (size_t)b * strideA;
    B += (size_t)b * strideB;
    C += (size_t)b * strideC;

    const int tid  = threadIdx.x;
    const int tx   = tid & 15;
    const int ty   = tid >> 4;
    const int row0 = blockIdx.y * BM;
    const int col0 = blockIdx.x * BN;

    float acc[TM][TN] = {};

    for (int kt = 0; kt < K; kt += BK) {
        if (A_KM) {
            #pragma unroll
            for (int i = tid; i < BM * BK; i += 256) {
                int m  = i / BK;
                int kk = i % BK;
                int gm = row0 + m;
                As[kk][m] = (gm < M) ? A[(size_t)gm * lda + (kt + kk)] : 0.0f;
            }
        } else {
            #pragma unroll
            for (int i = tid; i < BK * BM; i += 256) {
                int kk = i / BM;
                int m  = i % BM;
                int gm = row0 + m;
                As[kk][m] = (gm < M) ? A[(size_t)(kt + kk) * lda + gm] : 0.0f;
            }
        }
        if (B_KM) {
            #pragma unroll
            for (int i = tid; i < BN * BK; i += 256) {
                int n  = i / BK;
                int kk = i % BK;
                Bs[kk][n] = B[(size_t)(col0 + n) * ldb + (kt + kk)];
            }
        } else {
            #pragma unroll
            for (int i = tid; i < BK * BN; i += 256) {
                int kk = i / BN;
                int n  = i % BN;
                Bs[kk][n] = B[(size_t)(kt + kk) * ldb + (col0 + n)];
            }
        }
        __syncthreads();

        #pragma unroll
        for (int kk = 0; kk < BK; kk++) {
            float af[TM], bf[TN];
            #pragma unroll
            for (int i = 0; i < TM; i++) af[i] = As[kk][ty * TM + i];
            #pragma unroll
            for (int j = 0; j < TN; j++) bf[j] = Bs[kk][tx * TN + j];
            #pragma unroll
            for (int i = 0; i < TM; i++)
                #pragma unroll
                for (int j = 0; j < TN; j++)
                    acc[i][j] += af[i] * bf[j];
        }
        __syncthreads();
    }

    const float g = EPI ? gamma[0] : 0.0f;
    const float* Xb = EPI ? (X + (size_t)b * strideX) : nullptr;
    #pragma unroll
    for (int i = 0; i < TM; i++) {
        int gm = row0 + ty * TM + i;
        if (gm >= M) continue;
        #pragma unroll
        for (int j = 0; j < TN; j++) {
            int gn = col0 + tx * TN + j;
            float r = acc[i][j];
            if (EPI) r = g * r + Xb[(size_t)gm * ldc + gn];
            C[(size_t)gm * ldc + gn] = r;
        }
    }
}

// ===========================================================================
// TF32 tensor-core GEMM (for v and out GEMMs; 97 of 122 GFLOP).
//   mma.sync.aligned.m16n8k8.row.col.f32.tf32.tf32.f32
//   Block 128x128, 8 warps (4x2), warp tile 32x64 = 2(m16) x 8(n8) mma tiles.
//   Smem tiles stored [row][k] with pad->20 words: fragment loads hit 32
//   distinct banks (gid*20 + tig mod 32 is a permutation over the warp).
//   Inputs rounded to tf32 with cvt.rna during the gmem->smem stage.
// ===========================================================================
__device__ __forceinline__ unsigned f2tf32(float x) {
    unsigned r;
    asm("cvt.rna.tf32.f32 %0, %1;" : "=r"(r) : "f"(x));
    return r;
}

__device__ __forceinline__ void mma_tf32(float* c, const unsigned* a,
                                         unsigned b0, unsigned b1) {
    asm volatile(
        "mma.sync.aligned.m16n8k8.row.col.f32.tf32.tf32.f32 "
        "{%0,%1,%2,%3}, {%4,%5,%6,%7}, {%8,%9}, {%0,%1,%2,%3};"
        : "+f"(c[0]), "+f"(c[1]), "+f"(c[2]), "+f"(c[3])
        : "r"(a[0]), "r"(a[1]), "r"(a[2]), "r"(a[3]), "r"(b0), "r"(b1));
}

template <bool A_KM, bool B_KM, bool EPI>
__global__ void __launch_bounds__(256)
gemm_tf32_kernel(const float* __restrict__ A, int lda, long long strideA,
                 const float* __restrict__ B, int ldb, long long strideB,
                 float* __restrict__ C, int ldc, long long strideC,
                 int M, int N, int K,
                 const float* __restrict__ gamma,
                 const float* __restrict__ X, long long strideX)
{
    constexpr int BM = 128, BN = 128, BK = 16, BKP = 20;
    __shared__ unsigned As[BM * BKP];   // [m][k], tf32 bits
    __shared__ unsigned Bs[BN * BKP];   // [n][k], tf32 bits

    const int b = blockIdx.z;
    A += (size_t)b * strideA;
    B += (size_t)b * strideB;
    C += (size_t)b * strideC;

    const int tid  = threadIdx.x;
    const int warp = tid >> 5;
    const int lane = tid & 31;
    const int gid  = lane >> 2;   // group id (0..7)
    const int tig  = lane & 3;    // thread in group (0..3)
    const int wm   = warp >> 1;   // 0..3 -> 32-row slab
    const int wn   = warp & 1;    // 0..1 -> 64-col slab
    const int row0 = blockIdx.y * BM;
    const int col0 = blockIdx.x * BN;

    float acc[2][8][4];
    #pragma unroll
    for (int i = 0; i < 2; i++)
        #pragma unroll
        for (int j = 0; j < 8; j++)
            #pragma unroll
            for (int r = 0; r < 4; r++) acc[i][j][r] = 0.0f;

    for (int kt = 0; kt < K; kt += BK) {
        // ---- A tile -> As[m][k] ----
        if (A_KM) {
            #pragma unroll
            for (int i = tid; i < BM * BK; i += 256) {
                int m  = i >> 4;
                int kk = i & 15;
                int gm = row0 + m;
                float v = (gm < M) ? A[(size_t)gm * lda + (kt + kk)] : 0.0f;
                As[m * BKP + kk] = f2tf32(v);
            }
        } else {
            #pragma unroll
            for (int i = tid; i < BK * BM; i += 256) {
                int kk = i >> 7;
                int m  = i & 127;
                int gm = row0 + m;
                float v = (gm < M) ? A[(size_t)(kt + kk) * lda + gm] : 0.0f;
                As[m * BKP + kk] = f2tf32(v);
            }
        }
        // ---- B tile -> Bs[n][k] ----
        if (B_KM) {
            #pragma unroll
            for (int i = tid; i < BN * BK; i += 256) {
                int n  = i >> 4;
                int kk = i & 15;
                Bs[n * BKP + kk] = f2tf32(B[(size_t)(col0 + n) * ldb + (kt + kk)]);
            }
        } else {
            #pragma unroll
            for (int i = tid; i < BK * BN; i += 256) {
                int kk = i >> 7;
                int n  = i & 127;
                Bs[n * BKP + kk] = f2tf32(B[(size_t)(kt + kk) * ldb + (col0 + n)]);
            }
        }
        __syncthreads();

        #pragma unroll
        for (int kc = 0; kc < 2; kc++) {
            const int k0 = kc * 8;
            unsigned a[2][4];
            #pragma unroll
            for (int mt = 0; mt < 2; mt++) {
                int r = wm * 32 + mt * 16 + gid;
                a[mt][0] = As[r * BKP + k0 + tig];
                a[mt][1] = As[(r + 8) * BKP + k0 + tig];
                a[mt][2] = As[r * BKP + k0 + tig + 4];
                a[mt][3] = As[(r + 8) * BKP + k0 + tig + 4];
            }
            #pragma unroll
            for (int nt = 0; nt < 8; nt++) {
                int cn = wn * 64 + nt * 8 + gid;
                unsigned b0 = Bs[cn * BKP + k0 + tig];
                unsigned b1 = Bs[cn * BKP + k0 + tig + 4];
                #pragma unroll
                for (int mt = 0; mt < 2; mt++)
                    mma_tf32(acc[mt][nt], a[mt], b0, b1);
            }
        }
        __syncthreads();
    }

    // ---- epilogue ----
    const float g = EPI ? gamma[0] : 0.0f;
    const float* Xb = EPI ? (X + (size_t)b * strideX) : nullptr;
    #pragma unroll
    for (int mt = 0; mt < 2; mt++) {
        #pragma unroll
        for (int half = 0; half < 2; half++) {
            int gm = row0 + wm * 32 + mt * 16 + gid + half * 8;
            if (gm >= M) continue;
            #pragma unroll
            for (int nt = 0; nt < 8; nt++) {
                int gn = col0 + wn * 64 + nt * 8 + tig * 2;
                float r0 = acc[mt][nt][half * 2 + 0];
                float r1 = acc[mt][nt][half * 2 + 1];
                if (EPI) {
                    r0 = g * r0 + Xb[(size_t)gm * ldc + gn];
                    r1 = g * r1 + Xb[(size_t)gm * ldc + gn + 1];
                }
                C[(size_t)gm * ldc + gn]     = r0;
                C[(size_t)gm * ldc + gn + 1] = r1;
            }
        }
    }
}

// ---------------------------------------------------------------------------
// Row softmax over last dim of S[b][n][m]. 2304 = 9*256 floats in registers.
// ---------------------------------------------------------------------------
__global__ void __launch_bounds__(256)
softmax_kernel(float* __restrict__ S)
{
    const int n = blockIdx.x;
    const int b = blockIdx.y;
    float* row = S + ((size_t)b * NPIX + n) * NPIX;

    const int tid  = threadIdx.x;
    const int lane = tid & 31;
    const int warp = tid >> 5;

    float vals[9];
    float mx = -1e30f;
    #pragma unroll
    for (int j = 0; j < 9; j++) {
        vals[j] = row[tid + j * 256];
        mx = fmaxf(mx, vals[j]);
    }

    __shared__ float smax[8];
    __shared__ float ssum[8];
    __shared__ float sbc[2];

    #pragma unroll
    for (int o = 16; o > 0; o >>= 1)
        mx = fmaxf(mx, __shfl_xor_sync(0xffffffffu, mx, o));
    if (lane == 0) smax[warp] = mx;
    __syncthreads();
    if (tid == 0) {
        float m = smax[0];
        #pragma unroll
        for (int i = 1; i < 8; i++) m = fmaxf(m, smax[i]);
        sbc[0] = m;
    }
    __syncthreads();
    mx = sbc[0];

    float s = 0.0f;
    #pragma unroll
    for (int j = 0; j < 9; j++) {
        vals[j] = __expf(vals[j] - mx);
        s += vals[j];
    }
    #pragma unroll
    for (int o = 16; o > 0; o >>= 1)
        s += __shfl_xor_sync(0xffffffffu, s, o);
    if (lane == 0) ssum[warp] = s;
    __syncthreads();
    if (tid == 0) {
        float t = ssum[0];
        #pragma unroll
        for (int i = 1; i < 8; i++) t += ssum[i];
        sbc[1] = 1.0f / t;
    }
    __syncthreads();
    const float inv = sbc[1];

    #pragma unroll
    for (int j = 0; j < 9; j++)
        row[tid + j * 256] = vals[j] * inv;
}

// ---------------------------------------------------------------------------
// kernel_launch: x, Wq, Wk, Wv, gamma  ->  out (fp32, B*C*H*W)
// ---------------------------------------------------------------------------
extern "C" void kernel_launch(void* const* d_in, const int* in_sizes, int n_in,
                              void* d_out, int out_size)
{
    const float* x     = (const float*)d_in[0];
    const float* Wq    = (const float*)d_in[1];
    const float* Wk    = (const float*)d_in[2];
    const float* Wv    = (const float*)d_in[3];
    const float* gamma = (const float*)d_in[4];
    float* out = (float*)d_out;

    float *qp, *kp, *vp, *sp;
    cudaGetSymbolAddress((void**)&qp, g_q);
    cudaGetSymbolAddress((void**)&kp, g_k);
    cudaGetSymbolAddress((void**)&vp, g_v);
    cudaGetSymbolAddress((void**)&sp, g_s);

    const long long sx = (long long)CH * NPIX;
    const long long sq = (long long)IDIM * NPIX;
    const long long ss = (long long)NPIX * NPIX;
    const int NB = NPIX / 128;   // 18

    // q = Wq @ x  (fp32 — feeds softmax logits, keep exact)
    gemm_kernel<true, false, false><<<dim3(NB, 1, BATCH), 256>>>(
        Wq, CH, 0, x, NPIX, sx, qp, NPIX, sq,
        IDIM, NPIX, CH, nullptr, nullptr, 0);

    // k = Wk @ x  (fp32)
    gemm_kernel<true, false, false><<<dim3(NB, 1, BATCH), 256>>>(
        Wk, CH, 0, x, NPIX, sx, kp, NPIX, sq,
        IDIM, NPIX, CH, nullptr, nullptr, 0);

    // v = Wv @ x  (tf32 tensor cores)
    gemm_tf32_kernel<true, false, false><<<dim3(NB, CH / 128, BATCH), 256>>>(
        Wv, CH, 0, x, NPIX, sx, vp, NPIX, sx,
        CH, NPIX, CH, nullptr, nullptr, 0);

    // S[n,m] = q[:,n].k[:,m]  (fp32 — logits)
    gemm_kernel<false, false, false><<<dim3(NB, NB, BATCH), 256>>>(
        qp, NPIX, sq, kp, NPIX, sq, sp, NPIX, ss,
        NPIX, NPIX, IDIM, nullptr, nullptr, 0);

    // softmax over m
    softmax_kernel<<<dim3(NPIX, BATCH), 256>>>(sp);

    // out[c,n] = gamma * sum_m v[c,m]*P[n,m] + x[c,n]  (tf32 tensor cores)
    gemm_tf32_kernel<true, true, true><<<dim3(NB, CH / 128, BATCH), 256>>>(
        vp, NPIX, sx, sp, NPIX, ss, out, NPIX, sx,
        CH, NPIX, NPIX, gamma, x, sx);
}